// round 2
// baseline (speedup 1.0000x reference)
#include <cuda_runtime.h>
#include <math.h>

#define B 128
#define T 256
#define LAT 512
#define IND 9
#define NINTER 216
#define NCMD 143
#define NMOT 153
// xc row counts (real) and padded-to-4
#define XC0R 225
#define XC1R 359
#define XC2R 296
#define XC0P 228
#define XC1P 360
#define XC2P 296
#define NCTA 128
#define NTHR 256

// ---------------- device-global state (persists across launches; re-init each launch) ---------
__device__ float g_state[2 * LAT * B];   // double-buffered h, [buf][feat][b]
__device__ float g_xc0[XC0P * B];        // [xt(9) ; h_inter(216)][b]
__device__ float g_xc1[XC1P * B];        // [out0(216) ; h_cmd(143)][b]
__device__ float g_xc2[XC2P * B];        // [out1(143) ; h_motor(153)][b]
__device__ float g_xT[T * IND * B];      // transposed inputs [t][v][b]
__device__ unsigned g_count;             // grid barrier counter (monotonic per launch)

// ---------------- init kernel: reset state + transpose inputs (runs every launch) -------------
__global__ void init_kernel(const float* __restrict__ x, const float* __restrict__ dt) {
    int stride = gridDim.x * blockDim.x;
    int i0 = blockIdx.x * blockDim.x + threadIdx.x;
    if (i0 == 0) g_count = 0u;
    for (int i = i0; i < LAT * B; i += stride) g_state[i] = 0.f;
    for (int i = i0; i < XC0P * B; i += stride) g_xc0[i] = 0.f;
    for (int i = i0; i < XC1P * B; i += stride) g_xc1[i] = 0.f;
    for (int i = i0; i < XC2P * B; i += stride) g_xc2[i] = 0.f;
    for (int i = i0; i < T * IND * B; i += stride) {
        int b = i & (B - 1);
        int v = (i >> 7) % IND;
        int t = i / (IND * B);
        g_xT[i] = (v < 8) ? x[(b * T + t) * 8 + v] : dt[b * T + t];
    }
}

// ---------------- helpers ---------------------------------------------------------------------
__device__ __forceinline__ float sigm(float v) { return 1.f / (1.f + expf(-v)); }

__device__ __forceinline__ void grid_bar(unsigned& target) {
    target += NCTA;
    __syncthreads();
    if (threadIdx.x == 0) {
        __threadfence();                        // release: make this CTA's L2 writes visible
        atomicAdd(&g_count, 1u);
        while (*(volatile unsigned*)&g_count < target) { }
        __threadfence();                        // acquire
    }
    __syncthreads();
}

// load one CfC layer's (masked) weights for this CTA's <=2 neurons into smem
template<int INR, int INP, int NOUT>
__device__ void load_cfc(float* sw, float* sb,
                         const float* w1, const float* b1, const float* w2, const float* b2,
                         const float* wa, const float* ba, const float* wb, const float* bb,
                         const int* mask, int cta, int tid) {
    for (int i = tid; i < 8 * INP; i += NTHR) {
        int row = i / INP, j = i - row * INP;
        int n = row >> 2, m = row & 3;
        int o = (cta << 1) + n;
        float v = 0.f;
        if (o < NOUT && j < INR) {
            const float* ws = (m == 0) ? w1 : (m == 1) ? w2 : (m == 2) ? wa : wb;
            v = ws[o * INR + j];
            if (m < 2) v *= (float)mask[o * INR + j];
        }
        sw[i] = v;
    }
    if (tid < 8) {
        int n = tid >> 2, m = tid & 3;
        int o = (cta << 1) + n;
        sb[tid] = (o < NOUT) ? ((m == 0) ? b1 : (m == 1) ? b2 : (m == 2) ? ba : bb)[o] : 0.f;
    }
}

// one CfC layer stage: 2 neurons/CTA, 4 mats each, inputs feature-major from xc
template<int INP, int NOUT>
__device__ __forceinline__ void cfc_stage(const float* __restrict__ xc,
                                          const float* __restrict__ sw, const float* __restrict__ sb,
                                          float* s_part, int cta, int tid,
                                          float* __restrict__ gst, float* __restrict__ gxc) {
    const int jsl = tid >> 5, bg = tid & 31, b0 = bg << 2;
    float acc[8][4];
#pragma unroll
    for (int r = 0; r < 8; r++) { acc[r][0] = acc[r][1] = acc[r][2] = acc[r][3] = 0.f; }
    const int nch = INP >> 2;
    const int cpt = (nch + 7) >> 3;
    int c0 = jsl * cpt;
    int c1 = c0 + cpt; if (c1 > nch) c1 = nch;
    for (int ch = c0; ch < c1; ch++) {
        int j = ch << 2;
        float4 x0 = __ldcg((const float4*)(xc + (j + 0) * B + b0));
        float4 x1 = __ldcg((const float4*)(xc + (j + 1) * B + b0));
        float4 x2 = __ldcg((const float4*)(xc + (j + 2) * B + b0));
        float4 x3 = __ldcg((const float4*)(xc + (j + 3) * B + b0));
#pragma unroll
        for (int r = 0; r < 8; r++) {
            float4 w = *(const float4*)(sw + r * INP + j);
            acc[r][0] = fmaf(w.x, x0.x, acc[r][0]); acc[r][0] = fmaf(w.y, x1.x, acc[r][0]);
            acc[r][0] = fmaf(w.z, x2.x, acc[r][0]); acc[r][0] = fmaf(w.w, x3.x, acc[r][0]);
            acc[r][1] = fmaf(w.x, x0.y, acc[r][1]); acc[r][1] = fmaf(w.y, x1.y, acc[r][1]);
            acc[r][1] = fmaf(w.z, x2.y, acc[r][1]); acc[r][1] = fmaf(w.w, x3.y, acc[r][1]);
            acc[r][2] = fmaf(w.x, x0.z, acc[r][2]); acc[r][2] = fmaf(w.y, x1.z, acc[r][2]);
            acc[r][2] = fmaf(w.z, x2.z, acc[r][2]); acc[r][2] = fmaf(w.w, x3.z, acc[r][2]);
            acc[r][3] = fmaf(w.x, x0.w, acc[r][3]); acc[r][3] = fmaf(w.y, x1.w, acc[r][3]);
            acc[r][3] = fmaf(w.z, x2.w, acc[r][3]); acc[r][3] = fmaf(w.w, x3.w, acc[r][3]);
        }
    }
#pragma unroll
    for (int r = 0; r < 8; r++)
        *(float4*)(s_part + ((jsl << 3) + r) * B + b0) =
            make_float4(acc[r][0], acc[r][1], acc[r][2], acc[r][3]);
    __syncthreads();
    int n = tid >> 7, b = tid & 127;
    int o = (cta << 1) + n;
    if (o < NOUT) {
        float s0 = 0.f, s1 = 0.f, s2 = 0.f, s3 = 0.f;
#pragma unroll
        for (int sl = 0; sl < 8; sl++) {
            const float* p = s_part + ((sl << 3) + (n << 2)) * B + b;
            s0 += p[0]; s1 += p[B]; s2 += p[2 * B]; s3 += p[3 * B];
        }
        float ff1 = tanhf(s0 + sb[(n << 2) + 0]);
        float ff2 = tanhf(s1 + sb[(n << 2) + 1]);
        float ti = 1.f / (1.f + expf((s2 + sb[(n << 2) + 2]) - (s3 + sb[(n << 2) + 3])));
        float ov = ff1 + ti * (ff2 - ff1);
        __stcg(gst + o * B + b, ov);
        if (gxc) __stcg(gxc + o * B + b, ov);
    }
}

// ---------------- main persistent kernel ------------------------------------------------------
__global__ void __launch_bounds__(NTHR, 1) ncp_kernel(
    const float* __restrict__ lstm_wi, const float* __restrict__ lstm_wr, const float* __restrict__ lstm_bi,
    const float* __restrict__ w1_0, const float* __restrict__ b1_0, const float* __restrict__ w2_0, const float* __restrict__ b2_0,
    const float* __restrict__ wa_0, const float* __restrict__ ba_0, const float* __restrict__ wb_0, const float* __restrict__ bb_0,
    const float* __restrict__ w1_1, const float* __restrict__ b1_1, const float* __restrict__ w2_1, const float* __restrict__ b2_1,
    const float* __restrict__ wa_1, const float* __restrict__ ba_1, const float* __restrict__ wb_1, const float* __restrict__ bb_1,
    const float* __restrict__ w1_2, const float* __restrict__ b1_2, const float* __restrict__ w2_2, const float* __restrict__ b2_2,
    const float* __restrict__ wa_2, const float* __restrict__ ba_2, const float* __restrict__ wb_2, const float* __restrict__ bb_2,
    const int* __restrict__ m0, const int* __restrict__ m1, const int* __restrict__ m2,
    float* __restrict__ out) {
    extern __shared__ float sm[];
    float* s_wr  = sm;                       // 16*512
    float* s_wi  = s_wr + 16 * LAT;          // 16*12 (padded)
    float* s_bi  = s_wi + 16 * 12;           // 16
    float* s_c   = s_bi + 16;                // 4*128 (cell state, CTA-private)
    float* s_cw0 = s_c + 4 * B;              // 8*228
    float* s_cw1 = s_cw0 + 8 * XC0P;         // 8*360
    float* s_cw2 = s_cw1 + 8 * XC1P;         // 8*296
    float* s_cb0 = s_cw2 + 8 * XC2P;         // 8
    float* s_cb1 = s_cb0 + 8;
    float* s_cb2 = s_cb1 + 8;
    float* s_part = s_cb2 + 8;               // 16*8*128

    const int cta = blockIdx.x, tid = threadIdx.x;

    // ---- one-time weight staging (masked CfC weights; LSTM slice for 4 latent units) ----
    for (int idx = tid; idx < 16 * LAT; idx += NTHR) {
        int r = idx >> 9, j = idx & (LAT - 1);
        int gr = ((r >> 2) << 9) + (cta << 2) + (r & 3);   // gate*512 + unit
        s_wr[idx] = lstm_wr[gr * LAT + j];
    }
    for (int idx = tid; idx < 16 * 12; idx += NTHR) {
        int r = idx / 12, v = idx - r * 12;
        int gr = ((r >> 2) << 9) + (cta << 2) + (r & 3);
        s_wi[idx] = (v < IND) ? lstm_wi[gr * IND + v] : 0.f;
    }
    if (tid < 16) {
        int gr = ((tid >> 2) << 9) + (cta << 2) + (tid & 3);
        s_bi[tid] = lstm_bi[gr];
    }
    for (int i = tid; i < 4 * B; i += NTHR) s_c[i] = 0.f;
    load_cfc<XC0R, XC0P, NINTER>(s_cw0, s_cb0, w1_0, b1_0, w2_0, b2_0, wa_0, ba_0, wb_0, bb_0, m0, cta, tid);
    load_cfc<XC1R, XC1P, NCMD  >(s_cw1, s_cb1, w1_1, b1_1, w2_1, b2_1, wa_1, ba_1, wb_1, bb_1, m1, cta, tid);
    load_cfc<XC2R, XC2P, NMOT  >(s_cw2, s_cb2, w1_2, b1_2, w2_2, b2_2, wa_2, ba_2, wb_2, bb_2, m2, cta, tid);
    __syncthreads();

    int cur = 0;
    unsigned target = 0;

    for (int t = 0; t < T; t++) {
        const int nxt = cur ^ 1;
        // ================= Stage 1: LSTM (4 latent units per CTA) =================
        {
            // CTA 0 additionally stages xt into g_xc0[0:9] for layer 0 (consumed after bar1)
            if (cta == 0) {
                for (int i = tid; i < IND * B; i += NTHR)
                    __stcg(&g_xc0[i], g_xT[t * IND * B + i]);
            }
            const float* hcur = g_state + cur * LAT * B;
            const int jsl = tid >> 5, bg = tid & 31, b0 = bg << 2;
            float acc[16][4];
#pragma unroll
            for (int r = 0; r < 16; r++) { acc[r][0] = acc[r][1] = acc[r][2] = acc[r][3] = 0.f; }
            const int j0 = jsl << 6;
            for (int j = j0; j < j0 + 64; j += 4) {
                float4 h0 = __ldcg((const float4*)(hcur + (j + 0) * B + b0));
                float4 h1 = __ldcg((const float4*)(hcur + (j + 1) * B + b0));
                float4 h2 = __ldcg((const float4*)(hcur + (j + 2) * B + b0));
                float4 h3 = __ldcg((const float4*)(hcur + (j + 3) * B + b0));
#pragma unroll
                for (int r = 0; r < 16; r++) {
                    float4 w = *(const float4*)(s_wr + (r << 9) + j);
                    acc[r][0] = fmaf(w.x, h0.x, acc[r][0]); acc[r][0] = fmaf(w.y, h1.x, acc[r][0]);
                    acc[r][0] = fmaf(w.z, h2.x, acc[r][0]); acc[r][0] = fmaf(w.w, h3.x, acc[r][0]);
                    acc[r][1] = fmaf(w.x, h0.y, acc[r][1]); acc[r][1] = fmaf(w.y, h1.y, acc[r][1]);
                    acc[r][1] = fmaf(w.z, h2.y, acc[r][1]); acc[r][1] = fmaf(w.w, h3.y, acc[r][1]);
                    acc[r][2] = fmaf(w.x, h0.z, acc[r][2]); acc[r][2] = fmaf(w.y, h1.z, acc[r][2]);
                    acc[r][2] = fmaf(w.z, h2.z, acc[r][2]); acc[r][2] = fmaf(w.w, h3.z, acc[r][2]);
                    acc[r][3] = fmaf(w.x, h0.w, acc[r][3]); acc[r][3] = fmaf(w.y, h1.w, acc[r][3]);
                    acc[r][3] = fmaf(w.z, h2.w, acc[r][3]); acc[r][3] = fmaf(w.w, h3.w, acc[r][3]);
                }
            }
#pragma unroll
            for (int r = 0; r < 16; r++)
                *(float4*)(s_part + ((jsl << 4) + r) * B + b0) =
                    make_float4(acc[r][0], acc[r][1], acc[r][2], acc[r][3]);
            __syncthreads();
            // gate math: thread -> (uhalf, b); 2 units each
            {
                const int b = tid & 127, uh = tid >> 7;
                float xv[IND];
#pragma unroll
                for (int v = 0; v < IND; v++) xv[v] = g_xT[(t * IND + v) * B + b];
#pragma unroll
                for (int k = 0; k < 2; k++) {
                    int uidx = uh * 2 + k;
                    float zg[4];
#pragma unroll
                    for (int g = 0; g < 4; g++) {
                        int r = g * 4 + uidx;
                        float s = s_bi[r];
#pragma unroll
                        for (int v = 0; v < IND; v++) s = fmaf(s_wi[r * 12 + v], xv[v], s);
#pragma unroll
                        for (int sl = 0; sl < 8; sl++) s += s_part[((sl << 4) + r) * B + b];
                        zg[g] = s;
                    }
                    float cold = s_c[uidx * B + b];
                    float cnew = cold * sigm(zg[2] + 1.f) + tanhf(zg[0]) * sigm(zg[1]);
                    float hv = tanhf(cnew) * sigm(zg[3]);
                    s_c[uidx * B + b] = cnew;
                    int u = (cta << 2) + uidx;
                    float* dst;
                    if (u < NINTER)             dst = g_xc0 + (IND + u) * B + b;
                    else if (u < NINTER + NCMD) dst = g_xc1 + u * B + b;
                    else                        dst = g_xc2 + (u - NINTER) * B + b;
                    __stcg(dst, hv);
                }
            }
        }
        grid_bar(target);
        // ================= Stage 2..4: CfC layers =================
        cfc_stage<XC0P, NINTER>(g_xc0, s_cw0, s_cb0, s_part, cta, tid,
                                g_state + nxt * LAT * B, g_xc1);
        grid_bar(target);
        cfc_stage<XC1P, NCMD>(g_xc1, s_cw1, s_cb1, s_part, cta, tid,
                              g_state + nxt * LAT * B + NINTER * B, g_xc2);
        grid_bar(target);
        cfc_stage<XC2P, NMOT>(g_xc2, s_cw2, s_cb2, s_part, cta, tid,
                              g_state + nxt * LAT * B + (NINTER + NCMD) * B, (float*)0);
        grid_bar(target);
        cur = nxt;
    }

    // ---- write output: out[0 : B*LAT] = h (B,LAT row-major); out[B*LAT : ] = c ----
    if (tid < B) {
        const int b = tid;
        const float* hs = g_state + cur * LAT * B;   // cur == 0 after even T
        float4 hv, cv;
        hv.x = __ldcg(hs + ((cta << 2) + 0) * B + b);
        hv.y = __ldcg(hs + ((cta << 2) + 1) * B + b);
        hv.z = __ldcg(hs + ((cta << 2) + 2) * B + b);
        hv.w = __ldcg(hs + ((cta << 2) + 3) * B + b);
        *(float4*)(out + b * LAT + (cta << 2)) = hv;
        cv.x = s_c[0 * B + b]; cv.y = s_c[1 * B + b];
        cv.z = s_c[2 * B + b]; cv.w = s_c[3 * B + b];
        *(float4*)(out + LAT * B + b * LAT + (cta << 2)) = cv;
    }
}

// ---------------- launch ----------------------------------------------------------------------
#define SMEM_FLOATS (16*LAT + 16*12 + 16 + 4*B + 8*XC0P + 8*XC1P + 8*XC2P + 24 + 16*8*B)
#define SMEM_BYTES (SMEM_FLOATS * 4)

extern "C" void kernel_launch(void* const* d_in, const int* in_sizes, int n_in,
                              void* d_out, int out_size) {
    const float* x       = (const float*)d_in[0];
    const float* dt      = (const float*)d_in[1];
    const float* lstm_wi = (const float*)d_in[2];
    const float* lstm_wr = (const float*)d_in[3];
    const float* lstm_bi = (const float*)d_in[4];
    const float* w1_0 = (const float*)d_in[5];  const float* b1_0 = (const float*)d_in[6];
    const float* w2_0 = (const float*)d_in[7];  const float* b2_0 = (const float*)d_in[8];
    const float* wa_0 = (const float*)d_in[9];  const float* ba_0 = (const float*)d_in[10];
    const float* wb_0 = (const float*)d_in[11]; const float* bb_0 = (const float*)d_in[12];
    const float* w1_1 = (const float*)d_in[13]; const float* b1_1 = (const float*)d_in[14];
    const float* w2_1 = (const float*)d_in[15]; const float* b2_1 = (const float*)d_in[16];
    const float* wa_1 = (const float*)d_in[17]; const float* ba_1 = (const float*)d_in[18];
    const float* wb_1 = (const float*)d_in[19]; const float* bb_1 = (const float*)d_in[20];
    const float* w1_2 = (const float*)d_in[21]; const float* b1_2 = (const float*)d_in[22];
    const float* w2_2 = (const float*)d_in[23]; const float* b2_2 = (const float*)d_in[24];
    const float* wa_2 = (const float*)d_in[25]; const float* ba_2 = (const float*)d_in[26];
    const float* wb_2 = (const float*)d_in[27]; const float* bb_2 = (const float*)d_in[28];
    const int* m0 = (const int*)d_in[29];
    const int* m1 = (const int*)d_in[30];
    const int* m2 = (const int*)d_in[31];
    float* out = (float*)d_out;

    cudaFuncSetAttribute(ncp_kernel, cudaFuncAttributeMaxDynamicSharedMemorySize, SMEM_BYTES);

    init_kernel<<<256, 256>>>(x, dt);
    ncp_kernel<<<NCTA, NTHR, SMEM_BYTES>>>(
        lstm_wi, lstm_wr, lstm_bi,
        w1_0, b1_0, w2_0, b2_0, wa_0, ba_0, wb_0, bb_0,
        w1_1, b1_1, w2_1, b2_1, wa_1, ba_1, wb_1, bb_1,
        w1_2, b1_2, w2_2, b2_2, wa_2, ba_2, wb_2, bb_2,
        m0, m1, m2, out);
}

// round 6
// speedup vs baseline: 1.3402x; 1.3402x over previous
#include <cuda_runtime.h>
#include <math.h>

#define B 128
#define T 256
#define LAT 512
#define IND 9
#define NINTER 216
#define NCMD 143
#define NMOT 153
// xc row counts (real) and padded-to-4
#define XC0R 225
#define XC1R 359
#define XC2R 296
#define XC0P 228
#define XC1P 360
#define XC2P 296
#define NCTA 128
#define NTHR 512

typedef unsigned long long u64;

// ---------------- device-global state (persists across launches; re-init each launch) ---------
__device__ float g_state[2 * LAT * B];   // double-buffered h, [buf][feat][b]
__device__ float g_xc0[XC0P * B];        // [xt(9) ; h_inter(216)][b]
__device__ float g_xc1[XC1P * B];        // [out0(216) ; h_cmd(143)][b]
__device__ float g_xc2[XC2P * B];        // [out1(143) ; h_motor(153)][b]
__device__ float g_xT[T * IND * B];      // transposed inputs [t][v][b]
__device__ unsigned g_count;             // grid barrier counter (monotonic per launch)

// ---------------- init kernel: reset state + transpose inputs (runs every launch) -------------
__global__ void init_kernel(const float* __restrict__ x, const float* __restrict__ dt) {
    int stride = gridDim.x * blockDim.x;
    int i0 = blockIdx.x * blockDim.x + threadIdx.x;
    if (i0 == 0) g_count = 0u;
    for (int i = i0; i < LAT * B; i += stride) g_state[i] = 0.f;
    for (int i = i0; i < XC0P * B; i += stride) g_xc0[i] = 0.f;
    for (int i = i0; i < XC1P * B; i += stride) g_xc1[i] = 0.f;
    for (int i = i0; i < XC2P * B; i += stride) g_xc2[i] = 0.f;
    for (int i = i0; i < T * IND * B; i += stride) {
        int b = i & (B - 1);
        int v = (i >> 7) % IND;
        int t = i / (IND * B);
        g_xT[i] = (v < 8) ? x[(b * T + t) * 8 + v] : dt[b * T + t];
    }
}

// ---------------- helpers ---------------------------------------------------------------------
__device__ __forceinline__ float sigm(float v) { return 1.f / (1.f + expf(-v)); }

// packed f32x2: duplicate scalar into both halves
__device__ __forceinline__ u64 pk2(float v) {
    u64 r;
    asm("mov.b64 %0, {%1, %1};" : "=l"(r) : "f"(v));
    return r;
}
// d = a * b + d  (two independent fp32 FMAs in one instruction: SASS FFMA2)
__device__ __forceinline__ void fma2(u64& d, u64 a, u64 b) {
    asm("fma.rn.f32x2 %0, %1, %2, %0;" : "+l"(d) : "l"(a), "l"(b));
}

__device__ __forceinline__ void grid_bar(unsigned& target) {
    target += NCTA;
    __syncthreads();
    if (threadIdx.x == 0) {
        __threadfence();                        // release
        atomicAdd(&g_count, 1u);
        while (*(volatile unsigned*)&g_count < target) { }
        __threadfence();                        // acquire
    }
    __syncthreads();
}

// load one CfC layer's (masked) weights for this CTA's <=2 neurons into smem,
// PACKED row-pair layout: sw[(pair*INP + j)*2 + (row&1)]
template<int INR, int INP, int NOUT>
__device__ void load_cfc(float* sw, float* sb,
                         const float* w1, const float* b1, const float* w2, const float* b2,
                         const float* wa, const float* ba, const float* wb, const float* bb,
                         const int* mask, int cta, int tid) {
    for (int i = tid; i < 8 * INP; i += NTHR) {
        int row = i / INP, j = i - row * INP;
        int n = row >> 2, m = row & 3;
        int o = (cta << 1) + n;
        float v = 0.f;
        if (o < NOUT && j < INR) {
            const float* ws = (m == 0) ? w1 : (m == 1) ? w2 : (m == 2) ? wa : wb;
            v = ws[o * INR + j];
            if (m < 2) v *= (float)mask[o * INR + j];
        }
        sw[(((row >> 1) * INP) + j) * 2 + (row & 1)] = v;
    }
    if (tid < 8) {
        int n = tid >> 2, m = tid & 3;
        int o = (cta << 1) + n;
        sb[tid] = (o < NOUT) ? ((m == 0) ? b1 : (m == 1) ? b2 : (m == 2) ? ba : bb)[o] : 0.f;
    }
}

// one CfC layer stage: 2 neurons/CTA, 4 mats each (8 rows = 4 row-pairs).
// 16 warps = 8 K-slices x 2 row-halves (2 pairs each). Packed f32x2 FMA.
template<int INP, int NOUT>
__device__ __forceinline__ void cfc_stage(const float* __restrict__ xc,
                                          const float* __restrict__ sw, const float* __restrict__ sb,
                                          float* s_part, int cta, int tid,
                                          float* __restrict__ gst, float* __restrict__ gxc) {
    const int w = tid >> 5, lane = tid & 31;
    const int jsl = w >> 1, rh = w & 1, b0 = lane << 2;
    u64 acc[2][4];
#pragma unroll
    for (int q = 0; q < 2; q++) { acc[q][0] = acc[q][1] = acc[q][2] = acc[q][3] = 0ULL; }
    const int nch = INP >> 2;
    const int cpt = (nch + 7) >> 3;
    int c0 = jsl * cpt;
    int c1 = c0 + cpt; if (c1 > nch) c1 = nch;
    for (int ch = c0; ch < c1; ch++) {
        int j = ch << 2;
        float4 x0 = __ldcg((const float4*)(xc + (j + 0) * B + b0));
        float4 x1 = __ldcg((const float4*)(xc + (j + 1) * B + b0));
        float4 x2 = __ldcg((const float4*)(xc + (j + 2) * B + b0));
        float4 x3 = __ldcg((const float4*)(xc + (j + 3) * B + b0));
        u64 xx0[4], xx1[4], xx2[4], xx3[4];
        xx0[0] = pk2(x0.x); xx0[1] = pk2(x0.y); xx0[2] = pk2(x0.z); xx0[3] = pk2(x0.w);
        xx1[0] = pk2(x1.x); xx1[1] = pk2(x1.y); xx1[2] = pk2(x1.z); xx1[3] = pk2(x1.w);
        xx2[0] = pk2(x2.x); xx2[1] = pk2(x2.y); xx2[2] = pk2(x2.z); xx2[3] = pk2(x2.w);
        xx3[0] = pk2(x3.x); xx3[1] = pk2(x3.y); xx3[2] = pk2(x3.z); xx3[3] = pk2(x3.w);
#pragma unroll
        for (int q = 0; q < 2; q++) {
            const int p = rh * 2 + q;
            const ulonglong2* wp = (const ulonglong2*)(sw + (p * INP + j) * 2);
            ulonglong2 wA = wp[0], wB = wp[1];
#pragma unroll
            for (int b = 0; b < 4; b++) {
                fma2(acc[q][b], wA.x, xx0[b]);
                fma2(acc[q][b], wA.y, xx1[b]);
                fma2(acc[q][b], wB.x, xx2[b]);
                fma2(acc[q][b], wB.y, xx3[b]);
            }
        }
    }
    u64* sp = (u64*)s_part;
#pragma unroll
    for (int q = 0; q < 2; q++) {
        const int p = rh * 2 + q;
        *(ulonglong2*)(sp + (jsl * 4 + p) * B + b0)     = make_ulonglong2(acc[q][0], acc[q][1]);
        *(ulonglong2*)(sp + (jsl * 4 + p) * B + b0 + 2) = make_ulonglong2(acc[q][2], acc[q][3]);
    }
    __syncthreads();
    if (tid < 256) {
        int n = tid >> 7, b = tid & 127;
        int o = (cta << 1) + n;
        if (o < NOUT) {
            float s[4];
#pragma unroll
            for (int m = 0; m < 4; m++) {
                int pi = n * 2 + (m >> 1), sub = m & 1;
                float a = 0.f;
#pragma unroll
                for (int sl = 0; sl < 8; sl++)
                    a += s_part[((sl * 4 + pi) * B + b) * 2 + sub];
                s[m] = a;
            }
            float ff1 = tanhf(s[0] + sb[n * 4 + 0]);
            float ff2 = tanhf(s[1] + sb[n * 4 + 1]);
            float ti = 1.f / (1.f + expf((s[2] + sb[n * 4 + 2]) - (s[3] + sb[n * 4 + 3])));
            float ov = ff1 + ti * (ff2 - ff1);
            __stcg(gst + o * B + b, ov);
            if (gxc) __stcg(gxc + o * B + b, ov);
        }
    }
}

// ---------------- main persistent kernel ------------------------------------------------------
__global__ void __launch_bounds__(NTHR, 1) ncp_kernel(
    const float* __restrict__ lstm_wi, const float* __restrict__ lstm_wr, const float* __restrict__ lstm_bi,
    const float* __restrict__ w1_0, const float* __restrict__ b1_0, const float* __restrict__ w2_0, const float* __restrict__ b2_0,
    const float* __restrict__ wa_0, const float* __restrict__ ba_0, const float* __restrict__ wb_0, const float* __restrict__ bb_0,
    const float* __restrict__ w1_1, const float* __restrict__ b1_1, const float* __restrict__ w2_1, const float* __restrict__ b2_1,
    const float* __restrict__ wa_1, const float* __restrict__ ba_1, const float* __restrict__ wb_1, const float* __restrict__ bb_1,
    const float* __restrict__ w1_2, const float* __restrict__ b1_2, const float* __restrict__ w2_2, const float* __restrict__ b2_2,
    const float* __restrict__ wa_2, const float* __restrict__ ba_2, const float* __restrict__ wb_2, const float* __restrict__ bb_2,
    const int* __restrict__ m0, const int* __restrict__ m1, const int* __restrict__ m2,
    float* __restrict__ out) {
    extern __shared__ float sm[];
    float* s_wr  = sm;                       // 16*512 (packed pairs: [pair8][512] float2)
    float* s_wi  = s_wr + 16 * LAT;          // 16*12
    float* s_bi  = s_wi + 16 * 12;           // 16
    float* s_c   = s_bi + 16;                // 4*128
    float* s_cw0 = s_c + 4 * B;              // 8*228 (packed)
    float* s_cw1 = s_cw0 + 8 * XC0P;         // 8*360
    float* s_cw2 = s_cw1 + 8 * XC1P;         // 8*296
    float* s_cb0 = s_cw2 + 8 * XC2P;         // 8
    float* s_cb1 = s_cb0 + 8;
    float* s_cb2 = s_cb1 + 8;
    float* s_part = s_cb2 + 8;               // LSTM: [sl8][pair8][128] float2 = 16384 floats

    const int cta = blockIdx.x, tid = threadIdx.x;

    // ---- one-time weight staging: LSTM row-pair packed ----
    for (int idx = tid; idx < 16 * LAT; idx += NTHR) {
        int r = idx >> 9, j = idx & (LAT - 1);
        int gr = ((r >> 2) << 9) + (cta << 2) + (r & 3);   // gate*512 + unit
        s_wr[(((r >> 1) << 9) + j) * 2 + (r & 1)] = lstm_wr[gr * LAT + j];
    }
    for (int idx = tid; idx < 16 * 12; idx += NTHR) {
        int r = idx / 12, v = idx - r * 12;
        int gr = ((r >> 2) << 9) + (cta << 2) + (r & 3);
        s_wi[idx] = (v < IND) ? lstm_wi[gr * IND + v] : 0.f;
    }
    if (tid < 16) {
        int gr = ((tid >> 2) << 9) + (cta << 2) + (tid & 3);
        s_bi[tid] = lstm_bi[gr];
    }
    for (int i = tid; i < 4 * B; i += NTHR) s_c[i] = 0.f;
    load_cfc<XC0R, XC0P, NINTER>(s_cw0, s_cb0, w1_0, b1_0, w2_0, b2_0, wa_0, ba_0, wb_0, bb_0, m0, cta, tid);
    load_cfc<XC1R, XC1P, NCMD  >(s_cw1, s_cb1, w1_1, b1_1, w2_1, b2_1, wa_1, ba_1, wb_1, bb_1, m1, cta, tid);
    load_cfc<XC2R, XC2P, NMOT  >(s_cw2, s_cb2, w1_2, b1_2, w2_2, b2_2, wa_2, ba_2, wb_2, bb_2, m2, cta, tid);
    __syncthreads();

    int cur = 0;
    unsigned target = 0;

    for (int t = 0; t < T; t++) {
        const int nxt = cur ^ 1;
        // ================= Stage 1: LSTM (4 latent units per CTA) =================
        {
            if (cta == 0) {
                for (int i = tid; i < IND * B; i += NTHR)
                    __stcg(&g_xc0[i], g_xT[t * IND * B + i]);
            }
            const float* hcur = g_state + cur * LAT * B;
            const int w = tid >> 5, lane = tid & 31;
            const int jsl = w >> 1, rh = w & 1, b0 = lane << 2;
            u64 acc[4][4];
#pragma unroll
            for (int q = 0; q < 4; q++) { acc[q][0] = acc[q][1] = acc[q][2] = acc[q][3] = 0ULL; }
            const int j0 = jsl << 6;
            for (int j = j0; j < j0 + 64; j += 4) {
                float4 h0 = __ldcg((const float4*)(hcur + (j + 0) * B + b0));
                float4 h1 = __ldcg((const float4*)(hcur + (j + 1) * B + b0));
                float4 h2 = __ldcg((const float4*)(hcur + (j + 2) * B + b0));
                float4 h3 = __ldcg((const float4*)(hcur + (j + 3) * B + b0));
                u64 xx0[4], xx1[4], xx2[4], xx3[4];
                xx0[0] = pk2(h0.x); xx0[1] = pk2(h0.y); xx0[2] = pk2(h0.z); xx0[3] = pk2(h0.w);
                xx1[0] = pk2(h1.x); xx1[1] = pk2(h1.y); xx1[2] = pk2(h1.z); xx1[3] = pk2(h1.w);
                xx2[0] = pk2(h2.x); xx2[1] = pk2(h2.y); xx2[2] = pk2(h2.z); xx2[3] = pk2(h2.w);
                xx3[0] = pk2(h3.x); xx3[1] = pk2(h3.y); xx3[2] = pk2(h3.z); xx3[3] = pk2(h3.w);
#pragma unroll
                for (int q = 0; q < 4; q++) {
                    const int p = rh * 4 + q;
                    const ulonglong2* wp = (const ulonglong2*)(s_wr + ((p << 9) + j) * 2);
                    ulonglong2 wA = wp[0], wB = wp[1];
#pragma unroll
                    for (int b = 0; b < 4; b++) {
                        fma2(acc[q][b], wA.x, xx0[b]);
                        fma2(acc[q][b], wA.y, xx1[b]);
                        fma2(acc[q][b], wB.x, xx2[b]);
                        fma2(acc[q][b], wB.y, xx3[b]);
                    }
                }
            }
            u64* sp = (u64*)s_part;
#pragma unroll
            for (int q = 0; q < 4; q++) {
                const int p = rh * 4 + q;
                *(ulonglong2*)(sp + (jsl * 8 + p) * B + b0)     = make_ulonglong2(acc[q][0], acc[q][1]);
                *(ulonglong2*)(sp + (jsl * 8 + p) * B + b0 + 2) = make_ulonglong2(acc[q][2], acc[q][3]);
            }
            __syncthreads();
            // gate math: 512 threads = 4 units x 128 batch, 1 unit each
            {
                const int b = tid & 127, u = tid >> 7;
                float xv[IND];
#pragma unroll
                for (int v = 0; v < IND; v++) xv[v] = g_xT[(t * IND + v) * B + b];
                float zg[4];
#pragma unroll
                for (int g = 0; g < 4; g++) {
                    int r = g * 4 + u;
                    float s = s_bi[r];
#pragma unroll
                    for (int v = 0; v < IND; v++) s = fmaf(s_wi[r * 12 + v], xv[v], s);
                    int pi = r >> 1, sub = r & 1;
#pragma unroll
                    for (int sl = 0; sl < 8; sl++)
                        s += s_part[((sl * 8 + pi) * B + b) * 2 + sub];
                    zg[g] = s;
                }
                float cold = s_c[u * B + b];
                float cnew = cold * sigm(zg[2] + 1.f) + tanhf(zg[0]) * sigm(zg[1]);
                float hv = tanhf(cnew) * sigm(zg[3]);
                s_c[u * B + b] = cnew;
                int ug = (cta << 2) + u;
                float* dst;
                if (ug < NINTER)             dst = g_xc0 + (IND + ug) * B + b;
                else if (ug < NINTER + NCMD) dst = g_xc1 + ug * B + b;
                else                         dst = g_xc2 + (ug - NINTER) * B + b;
                __stcg(dst, hv);
            }
        }
        grid_bar(target);
        // ================= Stage 2..4: CfC layers =================
        cfc_stage<XC0P, NINTER>(g_xc0, s_cw0, s_cb0, s_part, cta, tid,
                                g_state + nxt * LAT * B, g_xc1);
        grid_bar(target);
        cfc_stage<XC1P, NCMD>(g_xc1, s_cw1, s_cb1, s_part, cta, tid,
                              g_state + nxt * LAT * B + NINTER * B, g_xc2);
        grid_bar(target);
        cfc_stage<XC2P, NMOT>(g_xc2, s_cw2, s_cb2, s_part, cta, tid,
                              g_state + nxt * LAT * B + (NINTER + NCMD) * B, (float*)0);
        grid_bar(target);
        cur = nxt;
    }

    // ---- write output: out[0 : B*LAT] = h (B,LAT row-major); out[B*LAT : ] = c ----
    if (tid < B) {
        const int b = tid;
        const float* hs = g_state + cur * LAT * B;
        float4 hv, cv;
        hv.x = __ldcg(hs + ((cta << 2) + 0) * B + b);
        hv.y = __ldcg(hs + ((cta << 2) + 1) * B + b);
        hv.z = __ldcg(hs + ((cta << 2) + 2) * B + b);
        hv.w = __ldcg(hs + ((cta << 2) + 3) * B + b);
        *(float4*)(out + b * LAT + (cta << 2)) = hv;
        cv.x = s_c[0 * B + b]; cv.y = s_c[1 * B + b];
        cv.z = s_c[2 * B + b]; cv.w = s_c[3 * B + b];
        *(float4*)(out + LAT * B + b * LAT + (cta << 2)) = cv;
    }
}

// ---------------- launch ----------------------------------------------------------------------
#define SMEM_FLOATS (16*LAT + 16*12 + 16 + 4*B + 8*XC0P + 8*XC1P + 8*XC2P + 24 + 16*8*B)
#define SMEM_BYTES (SMEM_FLOATS * 4)

extern "C" void kernel_launch(void* const* d_in, const int* in_sizes, int n_in,
                              void* d_out, int out_size) {
    const float* x       = (const float*)d_in[0];
    const float* dt      = (const float*)d_in[1];
    const float* lstm_wi = (const float*)d_in[2];
    const float* lstm_wr = (const float*)d_in[3];
    const float* lstm_bi = (const float*)d_in[4];
    const float* w1_0 = (const float*)d_in[5];  const float* b1_0 = (const float*)d_in[6];
    const float* w2_0 = (const float*)d_in[7];  const float* b2_0 = (const float*)d_in[8];
    const float* wa_0 = (const float*)d_in[9];  const float* ba_0 = (const float*)d_in[10];
    const float* wb_0 = (const float*)d_in[11]; const float* bb_0 = (const float*)d_in[12];
    const float* w1_1 = (const float*)d_in[13]; const float* b1_1 = (const float*)d_in[14];
    const float* w2_1 = (const float*)d_in[15]; const float* b2_1 = (const float*)d_in[16];
    const float* wa_1 = (const float*)d_in[17]; const float* ba_1 = (const float*)d_in[18];
    const float* wb_1 = (const float*)d_in[19]; const float* bb_1 = (const float*)d_in[20];
    const float* w1_2 = (const float*)d_in[21]; const float* b1_2 = (const float*)d_in[22];
    const float* w2_2 = (const float*)d_in[23]; const float* b2_2 = (const float*)d_in[24];
    const float* wa_2 = (const float*)d_in[25]; const float* ba_2 = (const float*)d_in[26];
    const float* wb_2 = (const float*)d_in[27]; const float* bb_2 = (const float*)d_in[28];
    const int* m0 = (const int*)d_in[29];
    const int* m1 = (const int*)d_in[30];
    const int* m2 = (const int*)d_in[31];
    float* out = (float*)d_out;

    cudaFuncSetAttribute(ncp_kernel, cudaFuncAttributeMaxDynamicSharedMemorySize, SMEM_BYTES);

    init_kernel<<<256, 256>>>(x, dt);
    ncp_kernel<<<NCTA, NTHR, SMEM_BYTES>>>(
        lstm_wi, lstm_wr, lstm_bi,
        w1_0, b1_0, w2_0, b2_0, wa_0, ba_0, wb_0, bb_0,
        w1_1, b1_1, w2_1, b2_1, wa_1, ba_1, wb_1, bb_1,
        w1_2, b1_2, w2_2, b2_2, wa_2, ba_2, wb_2, bb_2,
        m0, m1, m2, out);
}